// round 16
// baseline (speedup 1.0000x reference)
#include <cuda_runtime.h>
#include <cuda_bf16.h>
#include <cstdint>

#define MAXN 40000
#define MAXG 64
#define HDIM 128
#define BSTRIDE 64

__device__ float g_h[MAXN * HDIM];          // h' = (x@W) * dinv[row]
__device__ int   g_cnt[MAXN];               // zero-init; reset by k_fused each run
__device__ int   g_bucket[MAXN * BSTRIDE];  // per-dst edge buckets (src ids)
// W packed as uint4 fragments: idx4 = ((p*8+ntl)*8+kc)*32 + cq*8 + r
// n = p*64+ntl*8+r; k0 = kc*16+cq*2; k1 = kc*16+8+cq*2
// uint4 = { hi(W[k0..k0+1][n]), lo(W[k0..k0+1][n]), hi(W[k1..k1+1][n]), lo(W[k1..k1+1][n]) }
__device__ __align__(16) uint4 g_wpk4[4096];
__device__ float g_pool_add[MAXG * HDIM];   // zero-init; reset by k_mlp each run
__device__ int   g_pool_max[MAXG * HDIM];   // init by k_poolinit / reset by k_mlp
__device__ int   g_count[MAXG];             // zero-init; reset by k_mlp

__device__ __forceinline__ int enc_f(float f) {
    int i = __float_as_int(f);
    return i >= 0 ? i : (i ^ 0x7FFFFFFF);
}
__device__ __forceinline__ float dec_f(int i) {
    int j = i >= 0 ? i : (i ^ 0x7FFFFFFF);
    return __int_as_float(j);
}
__device__ __forceinline__ uint32_t pack_bf(float a, float b) {
    __nv_bfloat162 v = __floats2bfloat162_rn(a, b);
    return *(uint32_t*)&v;
}

__device__ __forceinline__ void mma_bf16(float* d, const uint32_t* a, uint32_t b0, uint32_t b1) {
    asm volatile(
        "mma.sync.aligned.m16n8k16.row.col.f32.bf16.bf16.f32 "
        "{%0,%1,%2,%3}, {%4,%5,%6,%7}, {%8,%9}, {%0,%1,%2,%3};"
        : "+f"(d[0]), "+f"(d[1]), "+f"(d[2]), "+f"(d[3])
        : "r"(a[0]), "r"(a[1]), "r"(a[2]), "r"(a[3]), "r"(b0), "r"(b1));
}

__device__ __forceinline__ void split_pack(float2 v, uint32_t& hi, uint32_t& lo) {
    float h0 = __bfloat162float(__float2bfloat16(v.x));
    float h1 = __bfloat162float(__float2bfloat16(v.y));
    hi = pack_bf(h0, h1);
    lo = pack_bf(v.x - h0, v.y - h1);
}

// hi/lo pair for two consecutive-k W elements at column n
__device__ __forceinline__ void wpair(const float* W, int k, int n, uint32_t& hi, uint32_t& lo) {
    float w0 = W[k * 128 + n];
    float w1 = W[(k + 1) * 128 + n];
    float h0 = __bfloat162float(__float2bfloat16(w0));
    float h1 = __bfloat162float(__float2bfloat16(w1));
    hi = pack_bf(h0, h1);
    lo = pack_bf(w0 - h0, w1 - h1);
}

// ---------------- launch 0: W pack (uint4 fragments) + bucket scatter ----------------
__global__ __launch_bounds__(256) void k_prep(const float* __restrict__ W,
                                              const int* __restrict__ ei, int E) {
    int i = blockIdx.x * 256 + threadIdx.x;
    if (i < 4096) {
        int r   = i & 7;
        int cq  = (i >> 3) & 3;
        int kc  = (i >> 5) & 7;
        int ntl = (i >> 8) & 7;
        int p   = i >> 11;
        int n  = p * 64 + ntl * 8 + r;
        int k0 = kc * 16 + cq * 2;
        int k1 = k0 + 8;
        uint4 q;
        wpair(W, k0, n, q.x, q.y);
        wpair(W, k1, n, q.z, q.w);
        g_wpk4[i] = q;
    }
    if (i < E) {
        int src = ei[i];
        int dst = ei[E + i];
        int pos = atomicAdd(&g_cnt[dst], 1);
        g_bucket[dst * BSTRIDE + pos] = src;
    }
}

// ---------------- launch 1: pool_max init ----------------
__global__ __launch_bounds__(256) void k_poolinit(int G) {
    int i = blockIdx.x * 256 + threadIdx.x;
    if (i < G * HDIM) g_pool_max[i] = (int)0x80000000;
}

// ---------------- launch 2: h' = (x @ W) * dinv, single pass, 64KB dyn smem ----------------
// grid = ceil(N/128), 256 threads = 8 warps; warp owns 16 rows, all 128 cols.
__global__ __launch_bounds__(256) void k_gemm_mma(const float* __restrict__ X, int N) {
    extern __shared__ __align__(16) uint4 sB4[];   // 4096 uint4 = 64 KB
    int tid = threadIdx.x;
    int wid = tid >> 5, lane = tid & 31;
    int r = lane >> 2;        // 0..7
    int cq = lane & 3;        // 0..3

    {
        const uint4* src = (const uint4*)g_wpk4;
#pragma unroll
        for (int q = 0; q < 16; q++) sB4[tid + q * 256] = src[tid + q * 256];
    }
    __syncthreads();

    int ra = blockIdx.x * 128 + wid * 16 + r;
    int rb = ra + 8;
    bool okA = ra < N, okB = rb < N;
    float dinvA = okA ? rsqrtf((float)g_cnt[ra] + 1.0f) : 0.f;
    float dinvB = okB ? rsqrtf((float)g_cnt[rb] + 1.0f) : 0.f;
    const float* pa = X + (size_t)ra * 128;
    const float* pb = X + (size_t)rb * 128;

    float acc[16][4];
#pragma unroll
    for (int nt = 0; nt < 16; nt++)
#pragma unroll
        for (int q = 0; q < 4; q++) acc[nt][q] = 0.f;

#pragma unroll 1
    for (int kc = 0; kc < 8; kc++) {
        int k0 = kc * 16 + cq * 2;
        float2 v0 = okA ? *(const float2*)(pa + k0)     : make_float2(0.f, 0.f);
        float2 v1 = okB ? *(const float2*)(pb + k0)     : make_float2(0.f, 0.f);
        float2 v2 = okA ? *(const float2*)(pa + k0 + 8) : make_float2(0.f, 0.f);
        float2 v3 = okB ? *(const float2*)(pb + k0 + 8) : make_float2(0.f, 0.f);
        uint32_t ahi[4], alo[4];
        split_pack(v0, ahi[0], alo[0]);
        split_pack(v1, ahi[1], alo[1]);
        split_pack(v2, ahi[2], alo[2]);
        split_pack(v3, ahi[3], alo[3]);

        const uint4* bp = sB4 + kc * 32 + cq * 8 + r;   // per-(nt) stride = 256 uint4
#pragma unroll
        for (int nt = 0; nt < 16; nt++) {
            uint4 q = bp[nt << 8];
            mma_bf16(acc[nt], ahi, q.x, q.z);   // hi*hi
            mma_bf16(acc[nt], ahi, q.y, q.w);   // hi*lo
            mma_bf16(acc[nt], alo, q.x, q.z);   // lo*hi
        }
    }

#pragma unroll
    for (int nt = 0; nt < 16; nt++) {
        int col = ((nt >> 3) << 6) + ((nt & 7) << 3) + cq * 2;
        if (okA) *(float2*)(g_h + (size_t)ra * 128 + col) =
            make_float2(acc[nt][0] * dinvA, acc[nt][1] * dinvA);
        if (okB) *(float2*)(g_h + (size_t)rb * 128 + col) =
            make_float2(acc[nt][2] * dinvB, acc[nt][3] * dinvB);
    }
}

// ---------------- launch 3 (profiled): fused bucket aggregate, MLP=8 batched gathers ----------------
__global__ __launch_bounds__(256) void k_fused(const int* __restrict__ batch,
                                               const float* __restrict__ bgcn,
                                               const float* __restrict__ gamma,
                                               const float* __restrict__ beta,
                                               int N) {
    __shared__ float s_sum[128];
    __shared__ int   s_max[128];
    __shared__ int   s_cnt;
    int node0 = blockIdx.x * 8;
    if (node0 >= N) return;
    int tid = threadIdx.x;
    int wid = tid >> 5, lane = tid & 31;

    int lastnode = min(node0 + 7, N - 1);
    int gid0 = batch[node0];
    bool uniform = (gid0 == batch[lastnode]);

    if (tid < 128) { s_sum[tid] = 0.f; s_max[tid] = (int)0x80000000; }
    if (tid == 0) s_cnt = 0;
    __syncthreads();

    int node = node0 + wid;
    if (node < N) {
        int deg = g_cnt[node];
        if (lane == 0) g_cnt[node] = 0;     // restore for next graph replay
        float dn = rsqrtf((float)deg + 1.0f);
        const int* bk = g_bucket + (size_t)node * BSTRIDE;
        float4 acc = *(const float4*)(g_h + (size_t)node * 128 + lane * 4);  // self term
        for (int base = 0; base < deg; base += 32) {
            int s = (base + lane < deg) ? bk[base + lane] : 0;
            int cnt = min(32, deg - base);
            int t = 0;
            for (; t + 8 <= cnt; t += 8) {
                int si[8];
#pragma unroll
                for (int u = 0; u < 8; u++) si[u] = __shfl_sync(0xFFFFFFFFu, s, t + u);
                float4 v[8];
#pragma unroll
                for (int u = 0; u < 8; u++)
                    v[u] = *(const float4*)(g_h + (size_t)si[u] * 128 + lane * 4);
                float4 p01 = make_float4(v[0].x + v[1].x, v[0].y + v[1].y, v[0].z + v[1].z, v[0].w + v[1].w);
                float4 p23 = make_float4(v[2].x + v[3].x, v[2].y + v[3].y, v[2].z + v[3].z, v[2].w + v[3].w);
                float4 p45 = make_float4(v[4].x + v[5].x, v[4].y + v[5].y, v[4].z + v[5].z, v[4].w + v[5].w);
                float4 p67 = make_float4(v[6].x + v[7].x, v[6].y + v[7].y, v[6].z + v[7].z, v[6].w + v[7].w);
                acc.x += (p01.x + p23.x) + (p45.x + p67.x);
                acc.y += (p01.y + p23.y) + (p45.y + p67.y);
                acc.z += (p01.z + p23.z) + (p45.z + p67.z);
                acc.w += (p01.w + p23.w) + (p45.w + p67.w);
            }
            for (; t + 4 <= cnt; t += 4) {
                int s0 = __shfl_sync(0xFFFFFFFFu, s, t);
                int s1 = __shfl_sync(0xFFFFFFFFu, s, t + 1);
                int s2 = __shfl_sync(0xFFFFFFFFu, s, t + 2);
                int s3 = __shfl_sync(0xFFFFFFFFu, s, t + 3);
                float4 a = *(const float4*)(g_h + (size_t)s0 * 128 + lane * 4);
                float4 b = *(const float4*)(g_h + (size_t)s1 * 128 + lane * 4);
                float4 c = *(const float4*)(g_h + (size_t)s2 * 128 + lane * 4);
                float4 d = *(const float4*)(g_h + (size_t)s3 * 128 + lane * 4);
                acc.x += (a.x + b.x) + (c.x + d.x);
                acc.y += (a.y + b.y) + (c.y + d.y);
                acc.z += (a.z + b.z) + (c.z + d.z);
                acc.w += (a.w + b.w) + (c.w + d.w);
            }
            for (; t < cnt; t++) {
                int ss = __shfl_sync(0xFFFFFFFFu, s, t);
                float4 v = *(const float4*)(g_h + (size_t)ss * 128 + lane * 4);
                acc.x += v.x; acc.y += v.y; acc.z += v.z; acc.w += v.w;
            }
        }
        float4 b4 = *(const float4*)(bgcn + lane * 4);
        float v0 = fmaxf(fmaf(acc.x, dn, b4.x), 0.f);
        float v1 = fmaxf(fmaf(acc.y, dn, b4.y), 0.f);
        float v2 = fmaxf(fmaf(acc.z, dn, b4.z), 0.f);
        float v3 = fmaxf(fmaf(acc.w, dn, b4.w), 0.f);

        float s  = v0 + v1 + v2 + v3;
        float sq = v0 * v0 + v1 * v1 + v2 * v2 + v3 * v3;
#pragma unroll
        for (int o = 16; o; o >>= 1) {
            s  += __shfl_xor_sync(0xFFFFFFFFu, s, o);
            sq += __shfl_xor_sync(0xFFFFFFFFu, sq, o);
        }
        float mean = s * (1.f / 128.f);
        float var  = sq * (1.f / 128.f) - mean * mean;
        float inv  = rsqrtf(var + 1e-5f);
        float4 gm = *(const float4*)(gamma + lane * 4);
        float4 bt = *(const float4*)(beta + lane * 4);
        float y0 = fmaf((v0 - mean) * inv, gm.x, bt.x);
        float y1 = fmaf((v1 - mean) * inv, gm.y, bt.y);
        float y2 = fmaf((v2 - mean) * inv, gm.z, bt.z);
        float y3 = fmaf((v3 - mean) * inv, gm.w, bt.w);

        if (uniform) {
            atomicAdd(&s_sum[lane * 4 + 0], y0);
            atomicAdd(&s_sum[lane * 4 + 1], y1);
            atomicAdd(&s_sum[lane * 4 + 2], y2);
            atomicAdd(&s_sum[lane * 4 + 3], y3);
            atomicMax(&s_max[lane * 4 + 0], enc_f(y0));
            atomicMax(&s_max[lane * 4 + 1], enc_f(y1));
            atomicMax(&s_max[lane * 4 + 2], enc_f(y2));
            atomicMax(&s_max[lane * 4 + 3], enc_f(y3));
            if (lane == 0) atomicAdd(&s_cnt, 1);
        } else {
            int gid = batch[node];
            float* pa = g_pool_add + (size_t)gid * 128 + lane * 4;
            atomicAdd(pa + 0, y0); atomicAdd(pa + 1, y1);
            atomicAdd(pa + 2, y2); atomicAdd(pa + 3, y3);
            int* pm = g_pool_max + (size_t)gid * 128 + lane * 4;
            atomicMax(pm + 0, enc_f(y0)); atomicMax(pm + 1, enc_f(y1));
            atomicMax(pm + 2, enc_f(y2)); atomicMax(pm + 3, enc_f(y3));
            if (lane == 0) atomicAdd(&g_count[gid], 1);
        }
    }
    __syncthreads();
    if (uniform && tid < 128) {
        atomicAdd(&g_pool_add[(size_t)gid0 * 128 + tid], s_sum[tid]);
        atomicMax(&g_pool_max[(size_t)gid0 * 128 + tid], s_max[tid]);
    }
    if (uniform && tid == 0 && s_cnt > 0) atomicAdd(&g_count[gid0], s_cnt);
}

// ---------------- launch 4: MLP head, 1024-thread k-parallel (+ pool state restore) ----------------
__global__ __launch_bounds__(1024) void k_mlp(const float* __restrict__ W1, const float* __restrict__ b1,
                                              const float* __restrict__ W2, const float* __restrict__ b2,
                                              const float* __restrict__ W3, const float* __restrict__ b3,
                                              float* __restrict__ out, int G) {
    __shared__ float sg[384];
    __shared__ float s_part[1024];
    __shared__ float s1[128];
    __shared__ float s2[64];
    int gid = blockIdx.x;
    int tid = threadIdx.x;
    int cnt = g_count[gid];
    float c = fmaxf((float)cnt, 1.f);
    if (tid < 128) {
        float add = g_pool_add[(size_t)gid * 128 + tid];
        float mx  = (cnt > 0) ? dec_f(g_pool_max[(size_t)gid * 128 + tid]) : 0.f;
        sg[tid]       = add / c;
        sg[128 + tid] = add;
        sg[256 + tid] = mx;
        g_pool_add[(size_t)gid * 128 + tid] = 0.f;
        g_pool_max[(size_t)gid * 128 + tid] = (int)0x80000000;
    }
    if (tid == 0) g_count[gid] = 0;
    __syncthreads();

    {
        int o = tid & 127;
        int q = tid >> 7;
        int k0 = q * 48;
        float a0 = 0.f, a1 = 0.f, a2 = 0.f, a3 = 0.f;
        const float* w = W1 + o;
#pragma unroll
        for (int k = k0; k < k0 + 48; k += 4) {
            a0 = fmaf(sg[k + 0], w[(size_t)(k + 0) * 128], a0);
            a1 = fmaf(sg[k + 1], w[(size_t)(k + 1) * 128], a1);
            a2 = fmaf(sg[k + 2], w[(size_t)(k + 2) * 128], a2);
            a3 = fmaf(sg[k + 3], w[(size_t)(k + 3) * 128], a3);
        }
        s_part[tid] = (a0 + a1) + (a2 + a3);
    }
    __syncthreads();
    if (tid < 128) {
        float v = b1[tid];
#pragma unroll
        for (int q = 0; q < 8; q++) v += s_part[tid + q * 128];
        s1[tid] = fmaxf(v, 0.f);
    }
    __syncthreads();

    {
        int o = tid & 63;
        int q = tid >> 6;
        int k0 = q * 8;
        float a0 = 0.f, a1 = 0.f;
        const float* w = W2 + o;
#pragma unroll
        for (int k = k0; k < k0 + 8; k += 2) {
            a0 = fmaf(s1[k + 0], w[(size_t)(k + 0) * 64], a0);
            a1 = fmaf(s1[k + 1], w[(size_t)(k + 1) * 64], a1);
        }
        s_part[tid] = a0 + a1;
    }
    __syncthreads();
    if (tid < 64) {
        float v = b2[tid];
#pragma unroll
        for (int q = 0; q < 16; q++) v += s_part[tid + q * 64];
        s2[tid] = fmaxf(v, 0.f);
    }
    __syncthreads();

    {
        int w = tid >> 5, lane = tid & 31;
        if (w < 10) {
            float a = s2[lane] * W3[(size_t)lane * 10 + w]
                    + s2[lane + 32] * W3[(size_t)(lane + 32) * 10 + w];
#pragma unroll
            for (int o = 16; o; o >>= 1) a += __shfl_xor_sync(0xFFFFFFFFu, a, o);
            if (lane == 0) out[gid * 10 + w] = a + b3[w];
        }
    }
}

extern "C" void kernel_launch(void* const* d_in, const int* in_sizes, int n_in,
                              void* d_out, int out_size) {
    const float* x     = (const float*)d_in[0];
    const int*   ei    = (const int*)d_in[1];
    const int*   batch = (const int*)d_in[2];
    const float* Wg    = (const float*)d_in[4];
    const float* bg    = (const float*)d_in[5];
    const float* gamma = (const float*)d_in[6];
    const float* beta  = (const float*)d_in[7];
    const float* W1    = (const float*)d_in[8];
    const float* b1    = (const float*)d_in[9];
    const float* W2    = (const float*)d_in[10];
    const float* b2    = (const float*)d_in[11];
    const float* W3    = (const float*)d_in[12];
    const float* b3    = (const float*)d_in[13];
    float* out = (float*)d_out;

    int N = in_sizes[0] / HDIM;
    int E = in_sizes[1] / 2;
    int G = out_size / 10;

    static bool attr_set = false;
    if (!attr_set) {
        cudaFuncSetAttribute(k_gemm_mma, cudaFuncAttributeMaxDynamicSharedMemorySize, 65536);
        attr_set = true;
    }

    k_prep<<<(E + 255) / 256, 256>>>(Wg, ei, E);               // idx 0: pack + scatter
    k_poolinit<<<(G * HDIM + 255) / 256, 256>>>(G);            // idx 1
    k_gemm_mma<<<(N + 127) / 128, 256, 65536>>>(x, N);         // idx 2
    k_fused<<<(N + 7) / 8, 256>>>(batch, bg, gamma, beta, N);  // idx 3 -> profiled
    k_mlp<<<G, 1024>>>(W1, b1, W2, b2, W3, b3, out, G);        // idx 4
}

// round 17
// speedup vs baseline: 1.1110x; 1.1110x over previous
#include <cuda_runtime.h>
#include <cuda_bf16.h>
#include <cstdint>

#define MAXN 40000
#define MAXG 64
#define HDIM 128
#define BSTRIDE 64

__device__ float g_h[MAXN * HDIM];          // h' = (x@W) * dinv[row]
__device__ int   g_cnt[MAXN];               // zero-init; reset by k_fused each run
__device__ int   g_bucket[MAXN * BSTRIDE];  // per-dst edge buckets (src ids)
// W packed, hi/lo interleaved (uint2): index i (i<8192): p=i>>12, kc=(i>>9)&7, ntl=(i>>6)&7,
// j=(i>>3)&7, r=i&7; k=kc*16+(j&3)*2+(j>>2)*8; n=p*64+ntl*8+r;
// g_wpk2[i] = { pack_bf16(W[k][n],W[k+1][n]), pack_bf16(resid...) }
__device__ __align__(16) uint2 g_wpk2[8192];
__device__ float g_pool_add[MAXG * HDIM];   // zero-init; reset by k_mlp each run
__device__ int   g_pool_max[MAXG * HDIM];   // init by k_poolinit / reset by k_mlp
__device__ int   g_count[MAXG];             // zero-init; reset by k_mlp

__device__ __forceinline__ int enc_f(float f) {
    int i = __float_as_int(f);
    return i >= 0 ? i : (i ^ 0x7FFFFFFF);
}
__device__ __forceinline__ float dec_f(int i) {
    int j = i >= 0 ? i : (i ^ 0x7FFFFFFF);
    return __int_as_float(j);
}
__device__ __forceinline__ uint32_t pack_bf(float a, float b) {
    __nv_bfloat162 v = __floats2bfloat162_rn(a, b);
    return *(uint32_t*)&v;
}

__device__ __forceinline__ void mma_bf16(float* d, const uint32_t* a, uint32_t b0, uint32_t b1) {
    asm volatile(
        "mma.sync.aligned.m16n8k16.row.col.f32.bf16.bf16.f32 "
        "{%0,%1,%2,%3}, {%4,%5,%6,%7}, {%8,%9}, {%0,%1,%2,%3};"
        : "+f"(d[0]), "+f"(d[1]), "+f"(d[2]), "+f"(d[3])
        : "r"(a[0]), "r"(a[1]), "r"(a[2]), "r"(a[3]), "r"(b0), "r"(b1));
}

__device__ __forceinline__ void split_pack(float2 v, uint32_t& hi, uint32_t& lo) {
    float h0 = __bfloat162float(__float2bfloat16(v.x));
    float h1 = __bfloat162float(__float2bfloat16(v.y));
    hi = pack_bf(h0, h1);
    lo = pack_bf(v.x - h0, v.y - h1);
}

// ---------------- launch 0: W split/pack (uint2) + bucket scatter ----------------
__global__ __launch_bounds__(256) void k_prep(const float* __restrict__ W,
                                              const int* __restrict__ ei, int E) {
    int i = blockIdx.x * 256 + threadIdx.x;
    if (i < 8192) {
        int p   = i >> 12;
        int kc  = (i >> 9) & 7;
        int ntl = (i >> 6) & 7;
        int j   = (i >> 3) & 7;
        int r   = i & 7;
        int k = kc * 16 + (j & 3) * 2 + (j >> 2) * 8;
        int n = p * 64 + ntl * 8 + r;
        float w0 = W[k * 128 + n];
        float w1 = W[(k + 1) * 128 + n];
        float h0 = __bfloat162float(__float2bfloat16(w0));
        float h1 = __bfloat162float(__float2bfloat16(w1));
        g_wpk2[i] = make_uint2(pack_bf(h0, h1), pack_bf(w0 - h0, w1 - h1));
    }
    if (i < E) {
        int src = ei[i];
        int dst = ei[E + i];
        int pos = atomicAdd(&g_cnt[dst], 1);
        g_bucket[dst * BSTRIDE + pos] = src;
    }
}

// ---------------- launch 1: pool_max init ----------------
__global__ __launch_bounds__(256) void k_poolinit(int G) {
    int i = blockIdx.x * 256 + threadIdx.x;
    if (i < G * HDIM) g_pool_max[i] = (int)0x80000000;
}

// ---------------- launch 2: h' = (x @ W) * dinv, single pass, 64KB dyn smem (measured-best) ----------------
__global__ __launch_bounds__(256) void k_gemm_mma(const float* __restrict__ X, int N) {
    extern __shared__ __align__(16) uint2 sB[];   // 8192 uint2 = 64 KB
    int tid = threadIdx.x;
    int wid = tid >> 5, lane = tid & 31;
    int r = lane >> 2;        // 0..7
    int cq = lane & 3;        // 0..3

    {
        const uint4* src = (const uint4*)g_wpk2;
        uint4* dst = (uint4*)sB;
#pragma unroll
        for (int q = 0; q < 16; q++) dst[tid + q * 256] = src[tid + q * 256];
    }
    __syncthreads();

    int ra = blockIdx.x * 128 + wid * 16 + r;
    int rb = ra + 8;
    bool okA = ra < N, okB = rb < N;
    float dinvA = okA ? rsqrtf((float)g_cnt[ra] + 1.0f) : 0.f;
    float dinvB = okB ? rsqrtf((float)g_cnt[rb] + 1.0f) : 0.f;
    const float* pa = X + (size_t)ra * 128;
    const float* pb = X + (size_t)rb * 128;

    float acc[16][4];
#pragma unroll
    for (int nt = 0; nt < 16; nt++)
#pragma unroll
        for (int q = 0; q < 4; q++) acc[nt][q] = 0.f;

#pragma unroll 1
    for (int kc = 0; kc < 8; kc++) {
        int k0 = kc * 16 + cq * 2;
        float2 v0 = okA ? *(const float2*)(pa + k0)     : make_float2(0.f, 0.f);
        float2 v1 = okB ? *(const float2*)(pb + k0)     : make_float2(0.f, 0.f);
        float2 v2 = okA ? *(const float2*)(pa + k0 + 8) : make_float2(0.f, 0.f);
        float2 v3 = okB ? *(const float2*)(pb + k0 + 8) : make_float2(0.f, 0.f);
        uint32_t ahi[4], alo[4];
        split_pack(v0, ahi[0], alo[0]);
        split_pack(v1, ahi[1], alo[1]);
        split_pack(v2, ahi[2], alo[2]);
        split_pack(v3, ahi[3], alo[3]);

        const uint2* b0p = sB + kc * 512 + cq * 8 + r;   // j = cq
        const uint2* b1p = b0p + 32;                     // j = cq+4
#pragma unroll
        for (int nt = 0; nt < 16; nt++) {
            int off = ((nt & 7) << 6) + ((nt >> 3) << 12);
            uint2 B0 = b0p[off];
            uint2 B1 = b1p[off];
            mma_bf16(acc[nt], ahi, B0.x, B1.x);   // hi*hi
            mma_bf16(acc[nt], ahi, B0.y, B1.y);   // hi*lo
            mma_bf16(acc[nt], alo, B0.x, B1.x);   // lo*hi
        }
    }

#pragma unroll
    for (int nt = 0; nt < 16; nt++) {
        int col = ((nt >> 3) << 6) + ((nt & 7) << 3) + cq * 2;
        if (okA) *(float2*)(g_h + (size_t)ra * 128 + col) =
            make_float2(acc[nt][0] * dinvA, acc[nt][1] * dinvA);
        if (okB) *(float2*)(g_h + (size_t)rb * 128 + col) =
            make_float2(acc[nt][2] * dinvB, acc[nt][3] * dinvB);
    }
}

// ---------------- launch 3: fused bucket aggregate, MLP=8 batched gathers ----------------
__global__ __launch_bounds__(256) void k_fused(const int* __restrict__ batch,
                                               const float* __restrict__ bgcn,
                                               const float* __restrict__ gamma,
                                               const float* __restrict__ beta,
                                               int N) {
    __shared__ float s_sum[128];
    __shared__ int   s_max[128];
    __shared__ int   s_cnt;
    int node0 = blockIdx.x * 8;
    if (node0 >= N) return;
    int tid = threadIdx.x;
    int wid = tid >> 5, lane = tid & 31;

    int lastnode = min(node0 + 7, N - 1);
    int gid0 = batch[node0];
    bool uniform = (gid0 == batch[lastnode]);

    if (tid < 128) { s_sum[tid] = 0.f; s_max[tid] = (int)0x80000000; }
    if (tid == 0) s_cnt = 0;
    __syncthreads();

    int node = node0 + wid;
    if (node < N) {
        int deg = g_cnt[node];
        if (lane == 0) g_cnt[node] = 0;     // restore for next graph replay
        float dn = rsqrtf((float)deg + 1.0f);
        const int* bk = g_bucket + (size_t)node * BSTRIDE;
        float4 acc = *(const float4*)(g_h + (size_t)node * 128 + lane * 4);  // self term
        for (int base = 0; base < deg; base += 32) {
            int s = (base + lane < deg) ? bk[base + lane] : 0;
            int cnt = min(32, deg - base);
            int t = 0;
            for (; t + 8 <= cnt; t += 8) {
                int si[8];
#pragma unroll
                for (int u = 0; u < 8; u++) si[u] = __shfl_sync(0xFFFFFFFFu, s, t + u);
                float4 v[8];
#pragma unroll
                for (int u = 0; u < 8; u++)
                    v[u] = *(const float4*)(g_h + (size_t)si[u] * 128 + lane * 4);
                float4 p01 = make_float4(v[0].x + v[1].x, v[0].y + v[1].y, v[0].z + v[1].z, v[0].w + v[1].w);
                float4 p23 = make_float4(v[2].x + v[3].x, v[2].y + v[3].y, v[2].z + v[3].z, v[2].w + v[3].w);
                float4 p45 = make_float4(v[4].x + v[5].x, v[4].y + v[5].y, v[4].z + v[5].z, v[4].w + v[5].w);
                float4 p67 = make_float4(v[6].x + v[7].x, v[6].y + v[7].y, v[6].z + v[7].z, v[6].w + v[7].w);
                acc.x += (p01.x + p23.x) + (p45.x + p67.x);
                acc.y += (p01.y + p23.y) + (p45.y + p67.y);
                acc.z += (p01.z + p23.z) + (p45.z + p67.z);
                acc.w += (p01.w + p23.w) + (p45.w + p67.w);
            }
            for (; t + 4 <= cnt; t += 4) {
                int s0 = __shfl_sync(0xFFFFFFFFu, s, t);
                int s1 = __shfl_sync(0xFFFFFFFFu, s, t + 1);
                int s2 = __shfl_sync(0xFFFFFFFFu, s, t + 2);
                int s3 = __shfl_sync(0xFFFFFFFFu, s, t + 3);
                float4 a = *(const float4*)(g_h + (size_t)s0 * 128 + lane * 4);
                float4 b = *(const float4*)(g_h + (size_t)s1 * 128 + lane * 4);
                float4 c = *(const float4*)(g_h + (size_t)s2 * 128 + lane * 4);
                float4 d = *(const float4*)(g_h + (size_t)s3 * 128 + lane * 4);
                acc.x += (a.x + b.x) + (c.x + d.x);
                acc.y += (a.y + b.y) + (c.y + d.y);
                acc.z += (a.z + b.z) + (c.z + d.z);
                acc.w += (a.w + b.w) + (c.w + d.w);
            }
            for (; t < cnt; t++) {
                int ss = __shfl_sync(0xFFFFFFFFu, s, t);
                float4 v = *(const float4*)(g_h + (size_t)ss * 128 + lane * 4);
                acc.x += v.x; acc.y += v.y; acc.z += v.z; acc.w += v.w;
            }
        }
        float4 b4 = *(const float4*)(bgcn + lane * 4);
        float v0 = fmaxf(fmaf(acc.x, dn, b4.x), 0.f);
        float v1 = fmaxf(fmaf(acc.y, dn, b4.y), 0.f);
        float v2 = fmaxf(fmaf(acc.z, dn, b4.z), 0.f);
        float v3 = fmaxf(fmaf(acc.w, dn, b4.w), 0.f);

        float s  = v0 + v1 + v2 + v3;
        float sq = v0 * v0 + v1 * v1 + v2 * v2 + v3 * v3;
#pragma unroll
        for (int o = 16; o; o >>= 1) {
            s  += __shfl_xor_sync(0xFFFFFFFFu, s, o);
            sq += __shfl_xor_sync(0xFFFFFFFFu, sq, o);
        }
        float mean = s * (1.f / 128.f);
        float var  = sq * (1.f / 128.f) - mean * mean;
        float inv  = rsqrtf(var + 1e-5f);
        float4 gm = *(const float4*)(gamma + lane * 4);
        float4 bt = *(const float4*)(beta + lane * 4);
        float y0 = fmaf((v0 - mean) * inv, gm.x, bt.x);
        float y1 = fmaf((v1 - mean) * inv, gm.y, bt.y);
        float y2 = fmaf((v2 - mean) * inv, gm.z, bt.z);
        float y3 = fmaf((v3 - mean) * inv, gm.w, bt.w);

        if (uniform) {
            atomicAdd(&s_sum[lane * 4 + 0], y0);
            atomicAdd(&s_sum[lane * 4 + 1], y1);
            atomicAdd(&s_sum[lane * 4 + 2], y2);
            atomicAdd(&s_sum[lane * 4 + 3], y3);
            atomicMax(&s_max[lane * 4 + 0], enc_f(y0));
            atomicMax(&s_max[lane * 4 + 1], enc_f(y1));
            atomicMax(&s_max[lane * 4 + 2], enc_f(y2));
            atomicMax(&s_max[lane * 4 + 3], enc_f(y3));
            if (lane == 0) atomicAdd(&s_cnt, 1);
        } else {
            int gid = batch[node];
            float* pa = g_pool_add + (size_t)gid * 128 + lane * 4;
            atomicAdd(pa + 0, y0); atomicAdd(pa + 1, y1);
            atomicAdd(pa + 2, y2); atomicAdd(pa + 3, y3);
            int* pm = g_pool_max + (size_t)gid * 128 + lane * 4;
            atomicMax(pm + 0, enc_f(y0)); atomicMax(pm + 1, enc_f(y1));
            atomicMax(pm + 2, enc_f(y2)); atomicMax(pm + 3, enc_f(y3));
            if (lane == 0) atomicAdd(&g_count[gid], 1);
        }
    }
    __syncthreads();
    if (uniform && tid < 128) {
        atomicAdd(&g_pool_add[(size_t)gid0 * 128 + tid], s_sum[tid]);
        atomicMax(&g_pool_max[(size_t)gid0 * 128 + tid], s_max[tid]);
    }
    if (uniform && tid == 0 && s_cnt > 0) atomicAdd(&g_count[gid0], s_cnt);
}

// ---------------- launch 4: MLP head, 1024-thread k-parallel (+ pool state restore) ----------------
__global__ __launch_bounds__(1024) void k_mlp(const float* __restrict__ W1, const float* __restrict__ b1,
                                              const float* __restrict__ W2, const float* __restrict__ b2,
                                              const float* __restrict__ W3, const float* __restrict__ b3,
                                              float* __restrict__ out, int G) {
    __shared__ float sg[384];
    __shared__ float s_part[1024];
    __shared__ float s1[128];
    __shared__ float s2[64];
    int gid = blockIdx.x;
    int tid = threadIdx.x;
    int cnt = g_count[gid];
    float c = fmaxf((float)cnt, 1.f);
    if (tid < 128) {
        float add = g_pool_add[(size_t)gid * 128 + tid];
        float mx  = (cnt > 0) ? dec_f(g_pool_max[(size_t)gid * 128 + tid]) : 0.f;
        sg[tid]       = add / c;
        sg[128 + tid] = add;
        sg[256 + tid] = mx;
        g_pool_add[(size_t)gid * 128 + tid] = 0.f;
        g_pool_max[(size_t)gid * 128 + tid] = (int)0x80000000;
    }
    if (tid == 0) g_count[gid] = 0;
    __syncthreads();

    {
        int o = tid & 127;
        int q = tid >> 7;
        int k0 = q * 48;
        float a0 = 0.f, a1 = 0.f, a2 = 0.f, a3 = 0.f;
        const float* w = W1 + o;
#pragma unroll
        for (int k = k0; k < k0 + 48; k += 4) {
            a0 = fmaf(sg[k + 0], w[(size_t)(k + 0) * 128], a0);
            a1 = fmaf(sg[k + 1], w[(size_t)(k + 1) * 128], a1);
            a2 = fmaf(sg[k + 2], w[(size_t)(k + 2) * 128], a2);
            a3 = fmaf(sg[k + 3], w[(size_t)(k + 3) * 128], a3);
        }
        s_part[tid] = (a0 + a1) + (a2 + a3);
    }
    __syncthreads();
    if (tid < 128) {
        float v = b1[tid];
#pragma unroll
        for (int q = 0; q < 8; q++) v += s_part[tid + q * 128];
        s1[tid] = fmaxf(v, 0.f);
    }
    __syncthreads();

    {
        int o = tid & 63;
        int q = tid >> 6;
        int k0 = q * 8;
        float a0 = 0.f, a1 = 0.f;
        const float* w = W2 + o;
#pragma unroll
        for (int k = k0; k < k0 + 8; k += 2) {
            a0 = fmaf(s1[k + 0], w[(size_t)(k + 0) * 64], a0);
            a1 = fmaf(s1[k + 1], w[(size_t)(k + 1) * 64], a1);
        }
        s_part[tid] = a0 + a1;
    }
    __syncthreads();
    if (tid < 64) {
        float v = b2[tid];
#pragma unroll
        for (int q = 0; q < 16; q++) v += s_part[tid + q * 64];
        s2[tid] = fmaxf(v, 0.f);
    }
    __syncthreads();

    {
        int w = tid >> 5, lane = tid & 31;
        if (w < 10) {
            float a = s2[lane] * W3[(size_t)lane * 10 + w]
                    + s2[lane + 32] * W3[(size_t)(lane + 32) * 10 + w];
#pragma unroll
            for (int o = 16; o; o >>= 1) a += __shfl_xor_sync(0xFFFFFFFFu, a, o);
            if (lane == 0) out[gid * 10 + w] = a + b3[w];
        }
    }
}

extern "C" void kernel_launch(void* const* d_in, const int* in_sizes, int n_in,
                              void* d_out, int out_size) {
    const float* x     = (const float*)d_in[0];
    const int*   ei    = (const int*)d_in[1];
    const int*   batch = (const int*)d_in[2];
    const float* Wg    = (const float*)d_in[4];
    const float* bg    = (const float*)d_in[5];
    const float* gamma = (const float*)d_in[6];
    const float* beta  = (const float*)d_in[7];
    const float* W1    = (const float*)d_in[8];
    const float* b1    = (const float*)d_in[9];
    const float* W2    = (const float*)d_in[10];
    const float* b2    = (const float*)d_in[11];
    const float* W3    = (const float*)d_in[12];
    const float* b3    = (const float*)d_in[13];
    float* out = (float*)d_out;

    int N = in_sizes[0] / HDIM;
    int E = in_sizes[1] / 2;
    int G = out_size / 10;

    static bool attr_set = false;
    if (!attr_set) {
        cudaFuncSetAttribute(k_gemm_mma, cudaFuncAttributeMaxDynamicSharedMemorySize, 65536);
        attr_set = true;
    }

    k_prep<<<(E + 255) / 256, 256>>>(Wg, ei, E);               // idx 0: pack + scatter
    k_poolinit<<<(G * HDIM + 255) / 256, 256>>>(G);            // idx 1
    k_gemm_mma<<<(N + 127) / 128, 256, 65536>>>(x, N);         // idx 2
    k_fused<<<(N + 7) / 8, 256>>>(batch, bg, gamma, beta, N);  // idx 3 -> profiled
    k_mlp<<<G, 1024>>>(W1, b1, W2, b2, W3, b3, out, G);        // idx 4
}